// round 13
// baseline (speedup 1.0000x reference)
#include <cuda_runtime.h>
#include <cuda_fp16.h>
#include <cstdint>

#define NB 32
#define C  512
#define K  64
#define P  3136
#define CK (C*K)        // 32768
#define PSPLIT 7
#define PCH (P/PSPLIT)  // 448

// Scratch (device globals; allocation forbidden elsewhere)
__device__ __align__(256) __half g_a[(size_t)NB * K * P];         // softmax probs f16 ~12.8MB
__device__ __align__(256) float g_part[(size_t)PSPLIT * NB * CK]; // vlad partials ~29.4MB
__device__ __align__(256) float g_asumP[PSPLIT * NB * K];
__device__ __align__(256) float g_rowsq[NB * C];
__device__ __align__(256) float g_inv[NB];

__device__ __forceinline__ void mma16_f16(float acc[4], uint32_t a0, uint32_t a1,
                                          uint32_t a2, uint32_t a3,
                                          uint32_t b0, uint32_t b1) {
    asm volatile(
        "mma.sync.aligned.m16n8k16.row.col.f32.f16.f16.f32 "
        "{%0,%1,%2,%3}, {%4,%5,%6,%7}, {%8,%9}, {%0,%1,%2,%3};"
        : "+f"(acc[0]), "+f"(acc[1]), "+f"(acc[2]), "+f"(acc[3])
        : "r"(a0), "r"(a1), "r"(a2), "r"(a3), "r"(b0), "r"(b1));
}
__device__ __forceinline__ void ldsm4t(uint32_t& r0, uint32_t& r1,
                                       uint32_t& r2, uint32_t& r3, uint32_t addr) {
    asm volatile("ldmatrix.sync.aligned.m8n8.x4.trans.shared.b16 {%0,%1,%2,%3}, [%4];"
                 : "=r"(r0), "=r"(r1), "=r"(r2), "=r"(r3) : "r"(addr));
}
__device__ __forceinline__ uint32_t smem_u32(const void* p) {
    uint32_t a;
    asm("{ .reg .u64 t; cvta.to.shared.u64 t, %1; cvt.u32.u64 %0, t; }" : "=r"(a) : "l"(p));
    return a;
}
__device__ __forceinline__ uint32_t pack2h(float v0, float v1) {
    const __half h0 = __float2half_rn(v0), h1 = __float2half_rn(v1);
    return (uint32_t)__half_as_ushort(h0) | ((uint32_t)__half_as_ushort(h1) << 16);
}

// ===================== GEMM1: logits, f16-3x + ldmatrix.trans, c-chunk 64 ====
// grid (25, 32). M=128 px x N=64 k; contraction C=512 in 8 chunks of 64.
// A: [64 c][136 halves] hi/lo (Ah@0 17408B, Al@17408); B: [64 k][72 halves]
// hi/lo (Bh@34816 9216B, Bl@44032). bias@53248. sL overlay [128][65]f @0.
#define AROWH 136
#define AROWB 272
#define G1_SMEM 53504
__global__ __launch_bounds__(256, 2) void k_logits_tc(
    const float* __restrict__ x, const float* __restrict__ w,
    const float* __restrict__ bias)
{
    extern __shared__ char sm[];
    uint32_t* Ah32 = (uint32_t*)sm;
    uint32_t* Al32 = (uint32_t*)(sm + 17408);
    uint32_t* Bh32 = (uint32_t*)(sm + 34816);
    uint32_t* Bl32 = (uint32_t*)(sm + 44032);
    float* sL = (float*)sm;                 // epilogue overlay [128][65]
    float* sBias = (float*)(sm + 53248);

    const int tid = threadIdx.x, lane = tid & 31, wid = tid >> 5;
    const int g = lane >> 2, t = lane & 3;
    const int wm = wid & 3, wn = wid >> 2;
    const int n = blockIdx.y, p0 = blockIdx.x * 128;

    if (tid < 64) sBias[tid] = bias[tid];

    const float* xn = x + (size_t)n * C * P;
    const int pp = 2 * (tid & 63);         // pixel pair
    const int cq = tid >> 6;               // 0..3 -> c rows cq*16..cq*16+15
    const bool pok = (p0 + pp) < P;

    const uint32_t smb = smem_u32(sm);
    const uint32_t a_lane_off =
        (uint32_t)(((lane & 7) + ((lane >> 4) & 1) * 8) * AROWB
                   + (wm * 32 + ((lane >> 3) & 1) * 8) * 2);

    float acc[2][4][4];
    #pragma unroll
    for (int mt = 0; mt < 2; mt++)
        #pragma unroll
        for (int nt = 0; nt < 4; nt++)
            #pragma unroll
            for (int q = 0; q < 4; q++) acc[mt][nt][q] = 0.f;

    float2 xv[16], wv[8];
    #pragma unroll
    for (int r = 0; r < 16; r++)
        xv[r] = pok ? *(const float2*)(xn + (size_t)(cq * 16 + r) * P + p0 + pp)
                    : make_float2(0.f, 0.f);
    #pragma unroll
    for (int r = 0; r < 8; r++)
        wv[r] = *(const float2*)(w + (size_t)(wid + 8 * r) * C + 2 * lane);

    for (int i = 0; i < 8; i++) {
        if (i) __syncthreads();
        #pragma unroll
        for (int r = 0; r < 16; r++) {
            const int row = cq * 16 + r;
            const float v0 = xv[r].x, v1 = xv[r].y;
            const float h0 = __half2float(__float2half_rn(v0));
            const float h1 = __half2float(__float2half_rn(v1));
            const int wd = row * (AROWH / 2) + (pp >> 1);
            Ah32[wd] = pack2h(h0, h1);
            Al32[wd] = pack2h(v0 - h0, v1 - h1);
        }
        #pragma unroll
        for (int r = 0; r < 8; r++) {
            const int k = wid + 8 * r;
            const float v0 = wv[r].x, v1 = wv[r].y;
            const float h0 = __half2float(__float2half_rn(v0));
            const float h1 = __half2float(__float2half_rn(v1));
            const int wd = k * 36 + lane;
            Bh32[wd] = pack2h(h0, h1);
            Bl32[wd] = pack2h(v0 - h0, v1 - h1);
        }
        __syncthreads();
        if (i + 1 < 8) {
            const int c0 = (i + 1) * 64;
            #pragma unroll
            for (int r = 0; r < 16; r++)
                xv[r] = pok ? *(const float2*)(xn + (size_t)(c0 + cq * 16 + r) * P + p0 + pp)
                            : make_float2(0.f, 0.f);
            #pragma unroll
            for (int r = 0; r < 8; r++)
                wv[r] = *(const float2*)(w + (size_t)(wid + 8 * r) * C + c0 + 2 * lane);
        }
        #pragma unroll
        for (int kk = 0; kk < 4; kk++) {
            uint32_t ah[2][4], al[2][4];
            #pragma unroll
            for (int mt = 0; mt < 2; mt++) {
                const uint32_t ad = smb + a_lane_off + mt * 32 + kk * 16 * AROWB;
                ldsm4t(ah[mt][0], ah[mt][1], ah[mt][2], ah[mt][3], ad);
                ldsm4t(al[mt][0], al[mt][1], al[mt][2], al[mt][3], ad + 17408);
            }
            #pragma unroll
            for (int nt = 0; nt < 4; nt++) {
                const int nb = (wn * 32 + nt * 8 + g) * 36 + kk * 8 + t;
                const uint32_t bh0 = Bh32[nb], bh1 = Bh32[nb + 4];
                const uint32_t bl0 = Bl32[nb], bl1 = Bl32[nb + 4];
                #pragma unroll
                for (int mt = 0; mt < 2; mt++) {
                    mma16_f16(acc[mt][nt], ah[mt][0], ah[mt][1], ah[mt][2], ah[mt][3], bh0, bh1);
                    mma16_f16(acc[mt][nt], ah[mt][0], ah[mt][1], ah[mt][2], ah[mt][3], bl0, bl1);
                    mma16_f16(acc[mt][nt], al[mt][0], al[mt][1], al[mt][2], al[mt][3], bh0, bh1);
                }
            }
        }
    }

    // epilogue: logits -> sL, softmax over k per pixel, write a as f16
    __syncthreads();
    #pragma unroll
    for (int mt = 0; mt < 2; mt++) {
        const int pr = wm * 32 + mt * 16 + g;
        #pragma unroll
        for (int nt = 0; nt < 4; nt++) {
            const int k0 = wn * 32 + nt * 8 + 2 * t;
            sL[pr * 65 + k0]           = acc[mt][nt][0] + sBias[k0];
            sL[pr * 65 + k0 + 1]       = acc[mt][nt][1] + sBias[k0 + 1];
            sL[(pr + 8) * 65 + k0]     = acc[mt][nt][2] + sBias[k0];
            sL[(pr + 8) * 65 + k0 + 1] = acc[mt][nt][3] + sBias[k0 + 1];
        }
    }
    __syncthreads();
    if (tid < 128 && p0 + tid < P) {
        const float* row = sL + tid * 65;
        float v[64], m = -1e30f;
        #pragma unroll
        for (int k = 0; k < 64; k++) { v[k] = row[k]; m = fmaxf(m, v[k]); }
        float s = 0.f;
        #pragma unroll
        for (int k = 0; k < 64; k++) { v[k] = __expf(v[k] - m); s += v[k]; }
        const float inv = 1.f / s;
        __half* ga = g_a + (size_t)n * K * P + p0 + tid;
        #pragma unroll
        for (int k = 0; k < 64; k++) ga[(size_t)k * P] = __float2half_rn(v[k] * inv);
    }
}

// ===================== GEMM2: vlad partials, f16 2-term, p-chunk 64 ==========
// grid (4, PSPLIT, 32). M=128 c x N=64 k; contraction 448 p in 7 chunks of 64.
// X: [128 c][72 halves] hi/lo (Xh@0 18432B, Xl@18432);
// A-probs: [64 k][72 halves] single plane (Pa@36864 9216B). Total 46080.
#define XW2 36
#define G2_SMEM 46080
__global__ __launch_bounds__(256, 2) void k_vlad_tc(const float* __restrict__ x)
{
    extern __shared__ char sm2[];
    uint32_t* Xh32 = (uint32_t*)sm2;
    uint32_t* Xl32 = (uint32_t*)(sm2 + 18432);
    uint32_t* Pa32 = (uint32_t*)(sm2 + 36864);

    const int tid = threadIdx.x, lane = tid & 31, wid = tid >> 5;
    const int g = lane >> 2, t = lane & 3;
    const int wm = wid & 3, wn = wid >> 2;
    const int n = blockIdx.z, sp = blockIdx.y, c0 = blockIdx.x * 128;
    const bool do_asum = (blockIdx.x == 0);

    const float* xn = x + ((size_t)n * C + c0) * P;
    const __half* an = g_a + (size_t)n * K * P;
    const int pb0 = sp * PCH;

    float acc[2][4][4];
    #pragma unroll
    for (int mt = 0; mt < 2; mt++)
        #pragma unroll
        for (int nt = 0; nt < 4; nt++)
            #pragma unroll
            for (int q = 0; q < 4; q++) acc[mt][nt][q] = 0.f;

    float asumL[8];
    #pragma unroll
    for (int r = 0; r < 8; r++) asumL[r] = 0.f;

    float2 xv[16];
    uint32_t av[8];
    #pragma unroll
    for (int r = 0; r < 16; r++)
        xv[r] = *(const float2*)(xn + (size_t)(wid + 8 * r) * P + pb0 + 2 * lane);
    #pragma unroll
    for (int r = 0; r < 8; r++)
        av[r] = *(const uint32_t*)(an + (size_t)(wid + 8 * r) * P + pb0 + 2 * lane);

    for (int i = 0; i < 7; i++) {
        if (i) __syncthreads();
        #pragma unroll
        for (int r = 0; r < 16; r++) {
            const int row = wid + 8 * r;
            const float v0 = xv[r].x, v1 = xv[r].y;
            const float h0 = __half2float(__float2half_rn(v0));
            const float h1 = __half2float(__float2half_rn(v1));
            const int wd = row * XW2 + lane;
            Xh32[wd] = pack2h(h0, h1);
            Xl32[wd] = pack2h(v0 - h0, v1 - h1);
        }
        #pragma unroll
        for (int r = 0; r < 8; r++) {
            const int row = wid + 8 * r;
            Pa32[row * XW2 + lane] = av[r];
            if (do_asum) {
                const __half2 h2 = *(const __half2*)&av[r];
                asumL[r] += __half2float(h2.x) + __half2float(h2.y);
            }
        }
        __syncthreads();
        if (i + 1 < 7) {
            const int pb = pb0 + (i + 1) * 64;
            #pragma unroll
            for (int r = 0; r < 16; r++)
                xv[r] = *(const float2*)(xn + (size_t)(wid + 8 * r) * P + pb + 2 * lane);
            #pragma unroll
            for (int r = 0; r < 8; r++)
                av[r] = *(const uint32_t*)(an + (size_t)(wid + 8 * r) * P + pb + 2 * lane);
        }
        #pragma unroll
        for (int kk = 0; kk < 4; kk++) {
            uint32_t ah[2][4], al[2][4];
            #pragma unroll
            for (int mt = 0; mt < 2; mt++) {
                const int r0 = (wm * 32 + mt * 16 + g) * XW2 + kk * 8 + t;
                const int r1 = r0 + 8 * XW2;
                ah[mt][0] = Xh32[r0];     ah[mt][1] = Xh32[r1];
                ah[mt][2] = Xh32[r0 + 4]; ah[mt][3] = Xh32[r1 + 4];
                al[mt][0] = Xl32[r0];     al[mt][1] = Xl32[r1];
                al[mt][2] = Xl32[r0 + 4]; al[mt][3] = Xl32[r1 + 4];
            }
            #pragma unroll
            for (int nt = 0; nt < 4; nt++) {
                const int nb = (wn * 32 + nt * 8 + g) * XW2 + kk * 8 + t;
                const uint32_t b0 = Pa32[nb], b1 = Pa32[nb + 4];
                #pragma unroll
                for (int mt = 0; mt < 2; mt++) {
                    mma16_f16(acc[mt][nt], ah[mt][0], ah[mt][1], ah[mt][2], ah[mt][3], b0, b1);
                    mma16_f16(acc[mt][nt], al[mt][0], al[mt][1], al[mt][2], al[mt][3], b0, b1);
                }
            }
        }
    }

    float* gp = g_part + ((size_t)sp * NB + n) * CK;
    #pragma unroll
    for (int mt = 0; mt < 2; mt++) {
        const int cr = c0 + wm * 32 + mt * 16 + g;
        #pragma unroll
        for (int nt = 0; nt < 4; nt++) {
            const int k0 = wn * 32 + nt * 8 + 2 * t;
            *(float2*)(gp + (size_t)cr * 64 + k0) =
                make_float2(acc[mt][nt][0], acc[mt][nt][1]);
            *(float2*)(gp + (size_t)(cr + 8) * 64 + k0) =
                make_float2(acc[mt][nt][2], acc[mt][nt][3]);
        }
    }

    if (do_asum) {
        #pragma unroll
        for (int r = 0; r < 8; r++) {
            float s = asumL[r];
            #pragma unroll
            for (int o = 16; o > 0; o >>= 1) s += __shfl_xor_sync(0xffffffffu, s, o);
            if (lane == 0) g_asumP[(sp * NB + n) * K + wid + 8 * r] = s;
        }
    }
}

// --------------- combine 7 partials + centroid correction + intra-norm
__global__ __launch_bounds__(256) void k_combine_intra(
    const float* __restrict__ cent, float* __restrict__ out)
{
    const int row = blockIdx.x * 8 + (threadIdx.x >> 5);   // n*512 + c
    const int n = row >> 9, c = row & 511;
    const int lane = threadIdx.x & 31;

    float v0 = 0.f, v1 = 0.f, a0 = 0.f, a1 = 0.f;
    #pragma unroll
    for (int s = 0; s < PSPLIT; s++) {
        const size_t b = ((size_t)s * NB + n) * CK + c * 64;
        v0 += g_part[b + lane];
        v1 += g_part[b + lane + 32];
        a0 += g_asumP[(s * NB + n) * K + lane];
        a1 += g_asumP[(s * NB + n) * K + lane + 32];
    }
    v0 -= cent[c * 64 + lane] * a0;
    v1 -= cent[c * 64 + lane + 32] * a1;

    float sq = v0 * v0 + v1 * v1;
    #pragma unroll
    for (int o = 16; o > 0; o >>= 1) sq += __shfl_xor_sync(0xffffffffu, sq, o);

    const float denom = fmaxf(sqrtf(sq), 1e-12f);
    const float inv = 1.f / denom;
    out[(size_t)n * CK + c * 64 + lane]      = v0 * inv;
    out[(size_t)n * CK + c * 64 + lane + 32] = v1 * inv;
    if (lane == 0) g_rowsq[row] = sq * inv * inv;
}

// --------------------- global norm: reduce then scale
__global__ __launch_bounds__(256) void k_norm() {
    const int n = blockIdx.x;
    const int t = threadIdx.x;
    __shared__ float red[256];
    red[t] = g_rowsq[n * 512 + t] + g_rowsq[n * 512 + 256 + t];
    __syncthreads();
    for (int o = 128; o > 0; o >>= 1) {
        if (t < o) red[t] += red[t + o];
        __syncthreads();
    }
    if (t == 0) g_inv[n] = 1.f / fmaxf(sqrtf(red[0]), 1e-12f);
}

__global__ __launch_bounds__(256) void k_scale(float* __restrict__ out) {
    const int n = blockIdx.y;
    const float inv = g_inv[n];
    float4* v = (float4*)(out + (size_t)n * CK + blockIdx.x * 4096);
    const int t = threadIdx.x;
    #pragma unroll
    for (int j = 0; j < 4; j++) {
        float4 u = v[t + 256 * j];
        u.x *= inv; u.y *= inv; u.z *= inv; u.w *= inv;
        v[t + 256 * j] = u;
    }
}

extern "C" void kernel_launch(void* const* d_in, const int* in_sizes, int n_in,
                              void* d_out, int out_size) {
    const float* x    = (const float*)d_in[0];   // (32,512,56,56)
    const float* cent = (const float*)d_in[1];   // (64,512)
    const float* w    = (const float*)d_in[2];   // (64,512)
    const float* b    = (const float*)d_in[3];   // (64,)
    float* out = (float*)d_out;                  // (32, 32768)

    cudaFuncSetAttribute(k_logits_tc, cudaFuncAttributeMaxDynamicSharedMemorySize, G1_SMEM);
    cudaFuncSetAttribute(k_vlad_tc,   cudaFuncAttributeMaxDynamicSharedMemorySize, G2_SMEM);

    k_logits_tc<<<dim3(25, 32), 256, G1_SMEM>>>(x, w, b);
    k_vlad_tc<<<dim3(4, PSPLIT, NB), 256, G2_SMEM>>>(x);
    k_combine_intra<<<NB * C / 8, 256>>>(cent, out);
    k_norm<<<NB, 256>>>();
    k_scale<<<dim3(8, NB), 256>>>(out);
}

// round 15
// speedup vs baseline: 1.4520x; 1.4520x over previous
#include <cuda_runtime.h>
#include <cuda_fp16.h>
#include <cstdint>

#define NB 32
#define C  512
#define K  64
#define P  3136
#define CK (C*K)        // 32768
#define PSPLIT 7
#define PCH (P/PSPLIT)  // 448

// Scratch (device globals; allocation forbidden elsewhere)
__device__ __align__(256) float g_a[(size_t)NB * K * P];          // softmax probs ~25.7MB
__device__ __align__(256) float g_part[(size_t)PSPLIT * NB * CK]; // vlad partials ~29.4MB
__device__ __align__(256) float g_asumP[PSPLIT * NB * K];
__device__ __align__(256) float g_rowsq[NB * C];
__device__ __align__(256) float g_inv[NB];

__device__ __forceinline__ void mma16_f16(float acc[4], uint32_t a0, uint32_t a1,
                                          uint32_t a2, uint32_t a3,
                                          uint32_t b0, uint32_t b1) {
    asm volatile(
        "mma.sync.aligned.m16n8k16.row.col.f32.f16.f16.f32 "
        "{%0,%1,%2,%3}, {%4,%5,%6,%7}, {%8,%9}, {%0,%1,%2,%3};"
        : "+f"(acc[0]), "+f"(acc[1]), "+f"(acc[2]), "+f"(acc[3])
        : "r"(a0), "r"(a1), "r"(a2), "r"(a3), "r"(b0), "r"(b1));
}
__device__ __forceinline__ void ldsm4t(uint32_t& r0, uint32_t& r1,
                                       uint32_t& r2, uint32_t& r3, uint32_t addr) {
    asm volatile("ldmatrix.sync.aligned.m8n8.x4.trans.shared.b16 {%0,%1,%2,%3}, [%4];"
                 : "=r"(r0), "=r"(r1), "=r"(r2), "=r"(r3) : "r"(addr));
}
__device__ __forceinline__ uint32_t smem_u32(const void* p) {
    uint32_t a;
    asm("{ .reg .u64 t; cvta.to.shared.u64 t, %1; cvt.u32.u64 %0, t; }" : "=r"(a) : "l"(p));
    return a;
}
__device__ __forceinline__ uint32_t pack2h(float v0, float v1) {
    const __half h0 = __float2half_rn(v0), h1 = __float2half_rn(v1);
    return (uint32_t)__half_as_ushort(h0) | ((uint32_t)__half_as_ushort(h1) << 16);
}

// ===================== GEMM1: logits, f16-3x + ldmatrix.trans, c-chunk 64 ====
// (byte-identical to round-12 proven version)
#define AROWH 136
#define AROWB 272
#define G1_SMEM 53504
__global__ __launch_bounds__(256, 2) void k_logits_tc(
    const float* __restrict__ x, const float* __restrict__ w,
    const float* __restrict__ bias)
{
    extern __shared__ char sm[];
    uint32_t* Ah32 = (uint32_t*)sm;
    uint32_t* Al32 = (uint32_t*)(sm + 17408);
    uint32_t* Bh32 = (uint32_t*)(sm + 34816);
    uint32_t* Bl32 = (uint32_t*)(sm + 44032);
    float* sL = (float*)sm;                 // epilogue overlay [128][65]
    float* sBias = (float*)(sm + 53248);

    const int tid = threadIdx.x, lane = tid & 31, wid = tid >> 5;
    const int g = lane >> 2, t = lane & 3;
    const int wm = wid & 3, wn = wid >> 2;
    const int n = blockIdx.y, p0 = blockIdx.x * 128;

    if (tid < 64) sBias[tid] = bias[tid];

    const float* xn = x + (size_t)n * C * P;
    const int pp = 2 * (tid & 63);         // pixel pair
    const int cq = tid >> 6;               // 0..3 -> c rows cq*16..cq*16+15
    const bool pok = (p0 + pp) < P;

    const uint32_t smb = smem_u32(sm);
    const uint32_t a_lane_off =
        (uint32_t)(((lane & 7) + ((lane >> 4) & 1) * 8) * AROWB
                   + (wm * 32 + ((lane >> 3) & 1) * 8) * 2);

    float acc[2][4][4];
    #pragma unroll
    for (int mt = 0; mt < 2; mt++)
        #pragma unroll
        for (int nt = 0; nt < 4; nt++)
            #pragma unroll
            for (int q = 0; q < 4; q++) acc[mt][nt][q] = 0.f;

    float2 xv[16], wv[8];
    #pragma unroll
    for (int r = 0; r < 16; r++)
        xv[r] = pok ? *(const float2*)(xn + (size_t)(cq * 16 + r) * P + p0 + pp)
                    : make_float2(0.f, 0.f);
    #pragma unroll
    for (int r = 0; r < 8; r++)
        wv[r] = *(const float2*)(w + (size_t)(wid + 8 * r) * C + 2 * lane);

    for (int i = 0; i < 8; i++) {
        if (i) __syncthreads();
        #pragma unroll
        for (int r = 0; r < 16; r++) {
            const int row = cq * 16 + r;
            const float v0 = xv[r].x, v1 = xv[r].y;
            const float h0 = __half2float(__float2half_rn(v0));
            const float h1 = __half2float(__float2half_rn(v1));
            const int wd = row * (AROWH / 2) + (pp >> 1);
            Ah32[wd] = pack2h(h0, h1);
            Al32[wd] = pack2h(v0 - h0, v1 - h1);
        }
        #pragma unroll
        for (int r = 0; r < 8; r++) {
            const int k = wid + 8 * r;
            const float v0 = wv[r].x, v1 = wv[r].y;
            const float h0 = __half2float(__float2half_rn(v0));
            const float h1 = __half2float(__float2half_rn(v1));
            const int wd = k * 36 + lane;
            Bh32[wd] = pack2h(h0, h1);
            Bl32[wd] = pack2h(v0 - h0, v1 - h1);
        }
        __syncthreads();
        if (i + 1 < 8) {
            const int c0 = (i + 1) * 64;
            #pragma unroll
            for (int r = 0; r < 16; r++)
                xv[r] = pok ? *(const float2*)(xn + (size_t)(c0 + cq * 16 + r) * P + p0 + pp)
                            : make_float2(0.f, 0.f);
            #pragma unroll
            for (int r = 0; r < 8; r++)
                wv[r] = *(const float2*)(w + (size_t)(wid + 8 * r) * C + c0 + 2 * lane);
        }
        #pragma unroll
        for (int kk = 0; kk < 4; kk++) {
            uint32_t ah[2][4], al[2][4];
            #pragma unroll
            for (int mt = 0; mt < 2; mt++) {
                const uint32_t ad = smb + a_lane_off + mt * 32 + kk * 16 * AROWB;
                ldsm4t(ah[mt][0], ah[mt][1], ah[mt][2], ah[mt][3], ad);
                ldsm4t(al[mt][0], al[mt][1], al[mt][2], al[mt][3], ad + 17408);
            }
            #pragma unroll
            for (int nt = 0; nt < 4; nt++) {
                const int nb = (wn * 32 + nt * 8 + g) * 36 + kk * 8 + t;
                const uint32_t bh0 = Bh32[nb], bh1 = Bh32[nb + 4];
                const uint32_t bl0 = Bl32[nb], bl1 = Bl32[nb + 4];
                #pragma unroll
                for (int mt = 0; mt < 2; mt++) {
                    mma16_f16(acc[mt][nt], ah[mt][0], ah[mt][1], ah[mt][2], ah[mt][3], bh0, bh1);
                    mma16_f16(acc[mt][nt], ah[mt][0], ah[mt][1], ah[mt][2], ah[mt][3], bl0, bl1);
                    mma16_f16(acc[mt][nt], al[mt][0], al[mt][1], al[mt][2], al[mt][3], bh0, bh1);
                }
            }
        }
    }

    // epilogue: logits -> sL, softmax over k per pixel
    __syncthreads();
    #pragma unroll
    for (int mt = 0; mt < 2; mt++) {
        const int pr = wm * 32 + mt * 16 + g;
        #pragma unroll
        for (int nt = 0; nt < 4; nt++) {
            const int k0 = wn * 32 + nt * 8 + 2 * t;
            sL[pr * 65 + k0]           = acc[mt][nt][0] + sBias[k0];
            sL[pr * 65 + k0 + 1]       = acc[mt][nt][1] + sBias[k0 + 1];
            sL[(pr + 8) * 65 + k0]     = acc[mt][nt][2] + sBias[k0];
            sL[(pr + 8) * 65 + k0 + 1] = acc[mt][nt][3] + sBias[k0 + 1];
        }
    }
    __syncthreads();
    if (tid < 128 && p0 + tid < P) {
        const float* row = sL + tid * 65;
        float v[64], m = -1e30f;
        #pragma unroll
        for (int k = 0; k < 64; k++) { v[k] = row[k]; m = fmaxf(m, v[k]); }
        float s = 0.f;
        #pragma unroll
        for (int k = 0; k < 64; k++) { v[k] = __expf(v[k] - m); s += v[k]; }
        const float inv = 1.f / s;
        float* ga = g_a + (size_t)n * K * P + p0 + tid;
        #pragma unroll
        for (int k = 0; k < 64; k++) ga[(size_t)k * P] = v[k] * inv;
    }
}

// ===================== GEMM2: vlad partials, f16 2-term, p-chunk 64 ==========
// grid (4, PSPLIT, 32). M=128 c x N=64 k; contraction 448 p in 7 chunks of 64.
// X: [128 c][72 halves] hi/lo (Xh@0 18432B, Xl@18432);
// A-probs: [64 k][72 halves] single plane f16 (Pa@36864 9216B). Total 46080.
// a converted float->f16 at staging; error ~2^-11 relative on a, well under 1e-3.
#define XW2 36
#define G2_SMEM 46080
__global__ __launch_bounds__(256, 2) void k_vlad_tc(const float* __restrict__ x)
{
    extern __shared__ char sm2[];
    uint32_t* Xh32 = (uint32_t*)sm2;
    uint32_t* Xl32 = (uint32_t*)(sm2 + 18432);
    uint32_t* Pa32 = (uint32_t*)(sm2 + 36864);

    const int tid = threadIdx.x, lane = tid & 31, wid = tid >> 5;
    const int g = lane >> 2, t = lane & 3;
    const int wm = wid & 3, wn = wid >> 2;
    const int n = blockIdx.z, sp = blockIdx.y, c0 = blockIdx.x * 128;
    const bool do_asum = (blockIdx.x == 0);

    const float* xn = x + ((size_t)n * C + c0) * P;
    const float* an = g_a + (size_t)n * K * P;
    const int pb0 = sp * PCH;

    float acc[2][4][4];
    #pragma unroll
    for (int mt = 0; mt < 2; mt++)
        #pragma unroll
        for (int nt = 0; nt < 4; nt++)
            #pragma unroll
            for (int q = 0; q < 4; q++) acc[mt][nt][q] = 0.f;

    float asumL[8];
    #pragma unroll
    for (int r = 0; r < 8; r++) asumL[r] = 0.f;

    float2 xv[16], av[8];
    #pragma unroll
    for (int r = 0; r < 16; r++)
        xv[r] = *(const float2*)(xn + (size_t)(wid + 8 * r) * P + pb0 + 2 * lane);
    #pragma unroll
    for (int r = 0; r < 8; r++)
        av[r] = *(const float2*)(an + (size_t)(wid + 8 * r) * P + pb0 + 2 * lane);

    for (int i = 0; i < 7; i++) {
        if (i) __syncthreads();
        #pragma unroll
        for (int r = 0; r < 16; r++) {
            const int row = wid + 8 * r;
            const float v0 = xv[r].x, v1 = xv[r].y;
            const float h0 = __half2float(__float2half_rn(v0));
            const float h1 = __half2float(__float2half_rn(v1));
            const int wd = row * XW2 + lane;
            Xh32[wd] = pack2h(h0, h1);
            Xl32[wd] = pack2h(v0 - h0, v1 - h1);
        }
        #pragma unroll
        for (int r = 0; r < 8; r++) {
            const int row = wid + 8 * r;
            const float a0 = av[r].x, a1 = av[r].y;
            Pa32[row * XW2 + lane] = pack2h(a0, a1);
            if (do_asum)
                asumL[r] += __half2float(__float2half_rn(a0))
                          + __half2float(__float2half_rn(a1));
        }
        __syncthreads();
        if (i + 1 < 7) {
            const int pb = pb0 + (i + 1) * 64;
            #pragma unroll
            for (int r = 0; r < 16; r++)
                xv[r] = *(const float2*)(xn + (size_t)(wid + 8 * r) * P + pb + 2 * lane);
            #pragma unroll
            for (int r = 0; r < 8; r++)
                av[r] = *(const float2*)(an + (size_t)(wid + 8 * r) * P + pb + 2 * lane);
        }
        #pragma unroll
        for (int kk = 0; kk < 4; kk++) {
            uint32_t ah[2][4], al[2][4];
            #pragma unroll
            for (int mt = 0; mt < 2; mt++) {
                const int r0 = (wm * 32 + mt * 16 + g) * XW2 + kk * 8 + t;
                const int r1 = r0 + 8 * XW2;
                ah[mt][0] = Xh32[r0];     ah[mt][1] = Xh32[r1];
                ah[mt][2] = Xh32[r0 + 4]; ah[mt][3] = Xh32[r1 + 4];
                al[mt][0] = Xl32[r0];     al[mt][1] = Xl32[r1];
                al[mt][2] = Xl32[r0 + 4]; al[mt][3] = Xl32[r1 + 4];
            }
            #pragma unroll
            for (int nt = 0; nt < 4; nt++) {
                const int nb = (wn * 32 + nt * 8 + g) * XW2 + kk * 8 + t;
                const uint32_t b0 = Pa32[nb], b1 = Pa32[nb + 4];
                #pragma unroll
                for (int mt = 0; mt < 2; mt++) {
                    mma16_f16(acc[mt][nt], ah[mt][0], ah[mt][1], ah[mt][2], ah[mt][3], b0, b1);
                    mma16_f16(acc[mt][nt], al[mt][0], al[mt][1], al[mt][2], al[mt][3], b0, b1);
                }
            }
        }
    }

    float* gp = g_part + ((size_t)sp * NB + n) * CK;
    #pragma unroll
    for (int mt = 0; mt < 2; mt++) {
        const int cr = c0 + wm * 32 + mt * 16 + g;
        #pragma unroll
        for (int nt = 0; nt < 4; nt++) {
            const int k0 = wn * 32 + nt * 8 + 2 * t;
            *(float2*)(gp + (size_t)cr * 64 + k0) =
                make_float2(acc[mt][nt][0], acc[mt][nt][1]);
            *(float2*)(gp + (size_t)(cr + 8) * 64 + k0) =
                make_float2(acc[mt][nt][2], acc[mt][nt][3]);
        }
    }

    if (do_asum) {
        #pragma unroll
        for (int r = 0; r < 8; r++) {
            float s = asumL[r];
            #pragma unroll
            for (int o = 16; o > 0; o >>= 1) s += __shfl_xor_sync(0xffffffffu, s, o);
            if (lane == 0) g_asumP[(sp * NB + n) * K + wid + 8 * r] = s;
        }
    }
}

// --------------- combine 7 partials + centroid correction + intra-norm
__global__ __launch_bounds__(256) void k_combine_intra(
    const float* __restrict__ cent, float* __restrict__ out)
{
    const int row = blockIdx.x * 8 + (threadIdx.x >> 5);   // n*512 + c
    const int n = row >> 9, c = row & 511;
    const int lane = threadIdx.x & 31;

    float v0 = 0.f, v1 = 0.f, a0 = 0.f, a1 = 0.f;
    #pragma unroll
    for (int s = 0; s < PSPLIT; s++) {
        const size_t b = ((size_t)s * NB + n) * CK + c * 64;
        v0 += g_part[b + lane];
        v1 += g_part[b + lane + 32];
        a0 += g_asumP[(s * NB + n) * K + lane];
        a1 += g_asumP[(s * NB + n) * K + lane + 32];
    }
    v0 -= cent[c * 64 + lane] * a0;
    v1 -= cent[c * 64 + lane + 32] * a1;

    float sq = v0 * v0 + v1 * v1;
    #pragma unroll
    for (int o = 16; o > 0; o >>= 1) sq += __shfl_xor_sync(0xffffffffu, sq, o);

    const float denom = fmaxf(sqrtf(sq), 1e-12f);
    const float inv = 1.f / denom;
    out[(size_t)n * CK + c * 64 + lane]      = v0 * inv;
    out[(size_t)n * CK + c * 64 + lane + 32] = v1 * inv;
    if (lane == 0) g_rowsq[row] = sq * inv * inv;
}

// --------------------- global norm: reduce then scale
__global__ __launch_bounds__(256) void k_norm() {
    const int n = blockIdx.x;
    const int t = threadIdx.x;
    __shared__ float red[256];
    red[t] = g_rowsq[n * 512 + t] + g_rowsq[n * 512 + 256 + t];
    __syncthreads();
    for (int o = 128; o > 0; o >>= 1) {
        if (t < o) red[t] += red[t + o];
        __syncthreads();
    }
    if (t == 0) g_inv[n] = 1.f / fmaxf(sqrtf(red[0]), 1e-12f);
}

__global__ __launch_bounds__(256) void k_scale(float* __restrict__ out) {
    const int n = blockIdx.y;
    const float inv = g_inv[n];
    float4* v = (float4*)(out + (size_t)n * CK + blockIdx.x * 4096);
    const int t = threadIdx.x;
    #pragma unroll
    for (int j = 0; j < 4; j++) {
        float4 u = v[t + 256 * j];
        u.x *= inv; u.y *= inv; u.z *= inv; u.w *= inv;
        v[t + 256 * j] = u;
    }
}

extern "C" void kernel_launch(void* const* d_in, const int* in_sizes, int n_in,
                              void* d_out, int out_size) {
    const float* x    = (const float*)d_in[0];   // (32,512,56,56)
    const float* cent = (const float*)d_in[1];   // (64,512)
    const float* w    = (const float*)d_in[2];   // (64,512)
    const float* b    = (const float*)d_in[3];   // (64,)
    float* out = (float*)d_out;                  // (32, 32768)

    cudaFuncSetAttribute(k_logits_tc, cudaFuncAttributeMaxDynamicSharedMemorySize, G1_SMEM);
    cudaFuncSetAttribute(k_vlad_tc,   cudaFuncAttributeMaxDynamicSharedMemorySize, G2_SMEM);

    k_logits_tc<<<dim3(25, 32), 256, G1_SMEM>>>(x, w, b);
    k_vlad_tc<<<dim3(4, PSPLIT, NB), 256, G2_SMEM>>>(x);
    k_combine_intra<<<NB * C / 8, 256>>>(cent, out);
    k_norm<<<NB, 256>>>();
    k_scale<<<dim3(8, NB), 256>>>(out);
}

// round 16
// speedup vs baseline: 1.6010x; 1.1026x over previous
#include <cuda_runtime.h>
#include <cuda_fp16.h>
#include <cstdint>

#define NB 32
#define C  512
#define K  64
#define P  3136
#define CK (C*K)        // 32768
#define PSPLIT 7
#define PCH (P/PSPLIT)  // 448

// Scratch (device globals; allocation forbidden elsewhere)
__device__ __align__(256) float g_a[(size_t)NB * K * P];          // softmax probs ~25.7MB
__device__ __align__(256) float g_part[(size_t)PSPLIT * NB * CK]; // vlad partials ~29.4MB
__device__ __align__(256) float g_asumP[PSPLIT * NB * K];
__device__ __align__(256) float g_rowsq[NB * C];
__device__ __align__(256) float g_inv[NB];

__device__ __forceinline__ void mma16_f16(float acc[4], uint32_t a0, uint32_t a1,
                                          uint32_t a2, uint32_t a3,
                                          uint32_t b0, uint32_t b1) {
    asm volatile(
        "mma.sync.aligned.m16n8k16.row.col.f32.f16.f16.f32 "
        "{%0,%1,%2,%3}, {%4,%5,%6,%7}, {%8,%9}, {%0,%1,%2,%3};"
        : "+f"(acc[0]), "+f"(acc[1]), "+f"(acc[2]), "+f"(acc[3])
        : "r"(a0), "r"(a1), "r"(a2), "r"(a3), "r"(b0), "r"(b1));
}
__device__ __forceinline__ void ldsm4t(uint32_t& r0, uint32_t& r1,
                                       uint32_t& r2, uint32_t& r3, uint32_t addr) {
    asm volatile("ldmatrix.sync.aligned.m8n8.x4.trans.shared.b16 {%0,%1,%2,%3}, [%4];"
                 : "=r"(r0), "=r"(r1), "=r"(r2), "=r"(r3) : "r"(addr));
}
__device__ __forceinline__ uint32_t smem_u32(const void* p) {
    uint32_t a;
    asm("{ .reg .u64 t; cvta.to.shared.u64 t, %1; cvt.u32.u64 %0, t; }" : "=r"(a) : "l"(p));
    return a;
}
__device__ __forceinline__ uint32_t pack2h(float v0, float v1) {
    const __half h0 = __float2half_rn(v0), h1 = __float2half_rn(v1);
    return (uint32_t)__half_as_ushort(h0) | ((uint32_t)__half_as_ushort(h1) << 16);
}

// ===================== GEMM1: logits, f16-3x + ldmatrix.trans, c-chunk 64 ====
// (byte-identical to round-12/15 proven version)
#define AROWH 136
#define AROWB 272
#define G1_SMEM 53504
__global__ __launch_bounds__(256, 2) void k_logits_tc(
    const float* __restrict__ x, const float* __restrict__ w,
    const float* __restrict__ bias)
{
    extern __shared__ char sm[];
    uint32_t* Ah32 = (uint32_t*)sm;
    uint32_t* Al32 = (uint32_t*)(sm + 17408);
    uint32_t* Bh32 = (uint32_t*)(sm + 34816);
    uint32_t* Bl32 = (uint32_t*)(sm + 44032);
    float* sL = (float*)sm;                 // epilogue overlay [128][65]
    float* sBias = (float*)(sm + 53248);

    const int tid = threadIdx.x, lane = tid & 31, wid = tid >> 5;
    const int g = lane >> 2, t = lane & 3;
    const int wm = wid & 3, wn = wid >> 2;
    const int n = blockIdx.y, p0 = blockIdx.x * 128;

    if (tid < 64) sBias[tid] = bias[tid];

    const float* xn = x + (size_t)n * C * P;
    const int pp = 2 * (tid & 63);         // pixel pair
    const int cq = tid >> 6;               // 0..3 -> c rows cq*16..cq*16+15
    const bool pok = (p0 + pp) < P;

    const uint32_t smb = smem_u32(sm);
    const uint32_t a_lane_off =
        (uint32_t)(((lane & 7) + ((lane >> 4) & 1) * 8) * AROWB
                   + (wm * 32 + ((lane >> 3) & 1) * 8) * 2);

    float acc[2][4][4];
    #pragma unroll
    for (int mt = 0; mt < 2; mt++)
        #pragma unroll
        for (int nt = 0; nt < 4; nt++)
            #pragma unroll
            for (int q = 0; q < 4; q++) acc[mt][nt][q] = 0.f;

    float2 xv[16], wv[8];
    #pragma unroll
    for (int r = 0; r < 16; r++)
        xv[r] = pok ? *(const float2*)(xn + (size_t)(cq * 16 + r) * P + p0 + pp)
                    : make_float2(0.f, 0.f);
    #pragma unroll
    for (int r = 0; r < 8; r++)
        wv[r] = *(const float2*)(w + (size_t)(wid + 8 * r) * C + 2 * lane);

    for (int i = 0; i < 8; i++) {
        if (i) __syncthreads();
        #pragma unroll
        for (int r = 0; r < 16; r++) {
            const int row = cq * 16 + r;
            const float v0 = xv[r].x, v1 = xv[r].y;
            const float h0 = __half2float(__float2half_rn(v0));
            const float h1 = __half2float(__float2half_rn(v1));
            const int wd = row * (AROWH / 2) + (pp >> 1);
            Ah32[wd] = pack2h(h0, h1);
            Al32[wd] = pack2h(v0 - h0, v1 - h1);
        }
        #pragma unroll
        for (int r = 0; r < 8; r++) {
            const int k = wid + 8 * r;
            const float v0 = wv[r].x, v1 = wv[r].y;
            const float h0 = __half2float(__float2half_rn(v0));
            const float h1 = __half2float(__float2half_rn(v1));
            const int wd = k * 36 + lane;
            Bh32[wd] = pack2h(h0, h1);
            Bl32[wd] = pack2h(v0 - h0, v1 - h1);
        }
        __syncthreads();
        if (i + 1 < 8) {
            const int c0 = (i + 1) * 64;
            #pragma unroll
            for (int r = 0; r < 16; r++)
                xv[r] = pok ? *(const float2*)(xn + (size_t)(c0 + cq * 16 + r) * P + p0 + pp)
                            : make_float2(0.f, 0.f);
            #pragma unroll
            for (int r = 0; r < 8; r++)
                wv[r] = *(const float2*)(w + (size_t)(wid + 8 * r) * C + c0 + 2 * lane);
        }
        #pragma unroll
        for (int kk = 0; kk < 4; kk++) {
            uint32_t ah[2][4], al[2][4];
            #pragma unroll
            for (int mt = 0; mt < 2; mt++) {
                const uint32_t ad = smb + a_lane_off + mt * 32 + kk * 16 * AROWB;
                ldsm4t(ah[mt][0], ah[mt][1], ah[mt][2], ah[mt][3], ad);
                ldsm4t(al[mt][0], al[mt][1], al[mt][2], al[mt][3], ad + 17408);
            }
            #pragma unroll
            for (int nt = 0; nt < 4; nt++) {
                const int nb = (wn * 32 + nt * 8 + g) * 36 + kk * 8 + t;
                const uint32_t bh0 = Bh32[nb], bh1 = Bh32[nb + 4];
                const uint32_t bl0 = Bl32[nb], bl1 = Bl32[nb + 4];
                #pragma unroll
                for (int mt = 0; mt < 2; mt++) {
                    mma16_f16(acc[mt][nt], ah[mt][0], ah[mt][1], ah[mt][2], ah[mt][3], bh0, bh1);
                    mma16_f16(acc[mt][nt], ah[mt][0], ah[mt][1], ah[mt][2], ah[mt][3], bl0, bl1);
                    mma16_f16(acc[mt][nt], al[mt][0], al[mt][1], al[mt][2], al[mt][3], bh0, bh1);
                }
            }
        }
    }

    // epilogue: logits -> sL, softmax over k per pixel
    __syncthreads();
    #pragma unroll
    for (int mt = 0; mt < 2; mt++) {
        const int pr = wm * 32 + mt * 16 + g;
        #pragma unroll
        for (int nt = 0; nt < 4; nt++) {
            const int k0 = wn * 32 + nt * 8 + 2 * t;
            sL[pr * 65 + k0]           = acc[mt][nt][0] + sBias[k0];
            sL[pr * 65 + k0 + 1]       = acc[mt][nt][1] + sBias[k0 + 1];
            sL[(pr + 8) * 65 + k0]     = acc[mt][nt][2] + sBias[k0];
            sL[(pr + 8) * 65 + k0 + 1] = acc[mt][nt][3] + sBias[k0 + 1];
        }
    }
    __syncthreads();
    if (tid < 128 && p0 + tid < P) {
        const float* row = sL + tid * 65;
        float v[64], m = -1e30f;
        #pragma unroll
        for (int k = 0; k < 64; k++) { v[k] = row[k]; m = fmaxf(m, v[k]); }
        float s = 0.f;
        #pragma unroll
        for (int k = 0; k < 64; k++) { v[k] = __expf(v[k] - m); s += v[k]; }
        const float inv = 1.f / s;
        float* ga = g_a + (size_t)n * K * P + p0 + tid;
        #pragma unroll
        for (int k = 0; k < 64; k++) ga[(size_t)k * P] = v[k] * inv;
    }
}

// ===================== GEMM2: vlad partials, f16 1-term, p-chunk 64 ==========
// grid (4, PSPLIT, 32). M=128 c x N=64 k; contraction 448 p in 7 chunks of 64.
// X: [128 c][72 halves] single f16 plane (Xh@0 18432B);
// A-probs: [64 k][72 halves] single f16 plane (Pa@18432 9216B). Total 27648.
// x rounded to f16 (2^-11 rel); probs near-one-hot so a-rounding is benign.
#define XW2 36
#define G2_SMEM 27648
__global__ __launch_bounds__(256, 2) void k_vlad_tc(const float* __restrict__ x)
{
    extern __shared__ char sm2[];
    uint32_t* Xh32 = (uint32_t*)sm2;
    uint32_t* Pa32 = (uint32_t*)(sm2 + 18432);

    const int tid = threadIdx.x, lane = tid & 31, wid = tid >> 5;
    const int g = lane >> 2, t = lane & 3;
    const int wm = wid & 3, wn = wid >> 2;
    const int n = blockIdx.z, sp = blockIdx.y, c0 = blockIdx.x * 128;
    const bool do_asum = (blockIdx.x == 0);

    const float* xn = x + ((size_t)n * C + c0) * P;
    const float* an = g_a + (size_t)n * K * P;
    const int pb0 = sp * PCH;

    float acc[2][4][4];
    #pragma unroll
    for (int mt = 0; mt < 2; mt++)
        #pragma unroll
        for (int nt = 0; nt < 4; nt++)
            #pragma unroll
            for (int q = 0; q < 4; q++) acc[mt][nt][q] = 0.f;

    float asumL[8];
    #pragma unroll
    for (int r = 0; r < 8; r++) asumL[r] = 0.f;

    float2 xv[16], av[8];
    #pragma unroll
    for (int r = 0; r < 16; r++)
        xv[r] = *(const float2*)(xn + (size_t)(wid + 8 * r) * P + pb0 + 2 * lane);
    #pragma unroll
    for (int r = 0; r < 8; r++)
        av[r] = *(const float2*)(an + (size_t)(wid + 8 * r) * P + pb0 + 2 * lane);

    for (int i = 0; i < 7; i++) {
        if (i) __syncthreads();
        #pragma unroll
        for (int r = 0; r < 16; r++) {
            const int row = wid + 8 * r;
            Xh32[row * XW2 + lane] = pack2h(xv[r].x, xv[r].y);
        }
        #pragma unroll
        for (int r = 0; r < 8; r++) {
            const int row = wid + 8 * r;
            const float a0 = av[r].x, a1 = av[r].y;
            Pa32[row * XW2 + lane] = pack2h(a0, a1);
            if (do_asum)
                asumL[r] += __half2float(__float2half_rn(a0))
                          + __half2float(__float2half_rn(a1));
        }
        __syncthreads();
        if (i + 1 < 7) {
            const int pb = pb0 + (i + 1) * 64;
            #pragma unroll
            for (int r = 0; r < 16; r++)
                xv[r] = *(const float2*)(xn + (size_t)(wid + 8 * r) * P + pb + 2 * lane);
            #pragma unroll
            for (int r = 0; r < 8; r++)
                av[r] = *(const float2*)(an + (size_t)(wid + 8 * r) * P + pb + 2 * lane);
        }
        #pragma unroll
        for (int kk = 0; kk < 4; kk++) {
            uint32_t ah[2][4];
            #pragma unroll
            for (int mt = 0; mt < 2; mt++) {
                const int r0 = (wm * 32 + mt * 16 + g) * XW2 + kk * 8 + t;
                const int r1 = r0 + 8 * XW2;
                ah[mt][0] = Xh32[r0];     ah[mt][1] = Xh32[r1];
                ah[mt][2] = Xh32[r0 + 4]; ah[mt][3] = Xh32[r1 + 4];
            }
            #pragma unroll
            for (int nt = 0; nt < 4; nt++) {
                const int nb = (wn * 32 + nt * 8 + g) * XW2 + kk * 8 + t;
                const uint32_t b0 = Pa32[nb], b1 = Pa32[nb + 4];
                #pragma unroll
                for (int mt = 0; mt < 2; mt++)
                    mma16_f16(acc[mt][nt], ah[mt][0], ah[mt][1], ah[mt][2], ah[mt][3], b0, b1);
            }
        }
    }

    float* gp = g_part + ((size_t)sp * NB + n) * CK;
    #pragma unroll
    for (int mt = 0; mt < 2; mt++) {
        const int cr = c0 + wm * 32 + mt * 16 + g;
        #pragma unroll
        for (int nt = 0; nt < 4; nt++) {
            const int k0 = wn * 32 + nt * 8 + 2 * t;
            *(float2*)(gp + (size_t)cr * 64 + k0) =
                make_float2(acc[mt][nt][0], acc[mt][nt][1]);
            *(float2*)(gp + (size_t)(cr + 8) * 64 + k0) =
                make_float2(acc[mt][nt][2], acc[mt][nt][3]);
        }
    }

    if (do_asum) {
        #pragma unroll
        for (int r = 0; r < 8; r++) {
            float s = asumL[r];
            #pragma unroll
            for (int o = 16; o > 0; o >>= 1) s += __shfl_xor_sync(0xffffffffu, s, o);
            if (lane == 0) g_asumP[(sp * NB + n) * K + wid + 8 * r] = s;
        }
    }
}

// --------------- combine 7 partials + centroid correction + intra-norm
__global__ __launch_bounds__(256) void k_combine_intra(
    const float* __restrict__ cent, float* __restrict__ out)
{
    const int row = blockIdx.x * 8 + (threadIdx.x >> 5);   // n*512 + c
    const int n = row >> 9, c = row & 511;
    const int lane = threadIdx.x & 31;

    float v0 = 0.f, v1 = 0.f, a0 = 0.f, a1 = 0.f;
    #pragma unroll
    for (int s = 0; s < PSPLIT; s++) {
        const size_t b = ((size_t)s * NB + n) * CK + c * 64;
        v0 += g_part[b + lane];
        v1 += g_part[b + lane + 32];
        a0 += g_asumP[(s * NB + n) * K + lane];
        a1 += g_asumP[(s * NB + n) * K + lane + 32];
    }
    v0 -= cent[c * 64 + lane] * a0;
    v1 -= cent[c * 64 + lane + 32] * a1;

    float sq = v0 * v0 + v1 * v1;
    #pragma unroll
    for (int o = 16; o > 0; o >>= 1) sq += __shfl_xor_sync(0xffffffffu, sq, o);

    const float denom = fmaxf(sqrtf(sq), 1e-12f);
    const float inv = 1.f / denom;
    out[(size_t)n * CK + c * 64 + lane]      = v0 * inv;
    out[(size_t)n * CK + c * 64 + lane + 32] = v1 * inv;
    if (lane == 0) g_rowsq[row] = sq * inv * inv;
}

// --------------------- global norm: reduce then scale
__global__ __launch_bounds__(256) void k_norm() {
    const int n = blockIdx.x;
    const int t = threadIdx.x;
    __shared__ float red[256];
    red[t] = g_rowsq[n * 512 + t] + g_rowsq[n * 512 + 256 + t];
    __syncthreads();
    for (int o = 128; o > 0; o >>= 1) {
        if (t < o) red[t] += red[t + o];
        __syncthreads();
    }
    if (t == 0) g_inv[n] = 1.f / fmaxf(sqrtf(red[0]), 1e-12f);
}

__global__ __launch_bounds__(256) void k_scale(float* __restrict__ out) {
    const int n = blockIdx.y;
    const float inv = g_inv[n];
    float4* v = (float4*)(out + (size_t)n * CK + blockIdx.x * 4096);
    const int t = threadIdx.x;
    #pragma unroll
    for (int j = 0; j < 4; j++) {
        float4 u = v[t + 256 * j];
        u.x *= inv; u.y *= inv; u.z *= inv; u.w *= inv;
        v[t + 256 * j] = u;
    }
}

extern "C" void kernel_launch(void* const* d_in, const int* in_sizes, int n_in,
                              void* d_out, int out_size) {
    const float* x    = (const float*)d_in[0];   // (32,512,56,56)
    const float* cent = (const float*)d_in[1];   // (64,512)
    const float* w    = (const float*)d_in[2];   // (64,512)
    const float* b    = (const float*)d_in[3];   // (64,)
    float* out = (float*)d_out;                  // (32, 32768)

    cudaFuncSetAttribute(k_logits_tc, cudaFuncAttributeMaxDynamicSharedMemorySize, G1_SMEM);
    cudaFuncSetAttribute(k_vlad_tc,   cudaFuncAttributeMaxDynamicSharedMemorySize, G2_SMEM);

    k_logits_tc<<<dim3(25, 32), 256, G1_SMEM>>>(x, w, b);
    k_vlad_tc<<<dim3(4, PSPLIT, NB), 256, G2_SMEM>>>(x);
    k_combine_intra<<<NB * C / 8, 256>>>(cent, out);
    k_norm<<<NB, 256>>>();
    k_scale<<<dim3(8, NB), 256>>>(out);
}